// round 5
// baseline (speedup 1.0000x reference)
#include <cuda_runtime.h>
#include <cstdint>
#include <cstddef>

#define SQ 4096
#define NB 64
#define HH 256
#define GC 1024   // 4 gates * 256 units, packed: pcol = j*4 + e  (e: 0=f,1=i,2=o,3=c)

typedef unsigned long long ull;

// ---------------- static device scratch (no allocations allowed) ----------------
__device__ float g_xg[(size_t)SQ * NB * GC];   // 1 GB input projections (+bias)
__device__ float g_Wp[HH * GC];                // packed W_all [k][pcol]
__device__ float g_Up[HH * GC];                // packed U_all [k][pcol]
__device__ float g_bp[GC];                     // packed bias
__device__ float g_hT[NB * HH];                // final hidden state

// ---------------- f32x2 helpers ----------------
__device__ __forceinline__ ull pk2(float x, float y) {
    ull r; asm("mov.b64 %0, {%1, %2};" : "=l"(r) : "f"(x), "f"(y)); return r;
}
__device__ __forceinline__ void fma2(ull& d, ull a, ull b) {
    asm("fma.rn.f32x2 %0, %1, %2, %0;" : "+l"(d) : "l"(a), "l"(b));
}
__device__ __forceinline__ float2 unpk(ull v) {
    float2 r; asm("mov.b64 {%0, %1}, %2;" : "=f"(r.x), "=f"(r.y) : "l"(v)); return r;
}
union F4U2 { float4 f4; ulonglong2 u2; };

// ---------------- phase 0: pack weights ----------------
__global__ void pack_kernel(const float* __restrict__ Wf, const float* __restrict__ Uf, const float* __restrict__ bf,
                            const float* __restrict__ Wi, const float* __restrict__ Ui, const float* __restrict__ bi,
                            const float* __restrict__ Wc, const float* __restrict__ Uc, const float* __restrict__ bc,
                            const float* __restrict__ Wo, const float* __restrict__ Uo, const float* __restrict__ bo)
{
    int i = blockIdx.x * blockDim.x + threadIdx.x;   // 0 .. 262143
    if (i < HH * GC) {
        int k = i >> 10, p = i & 1023;
        int j = p >> 2, e = p & 3;                   // e: 0=f,1=i,2=o,3=c
        const float* W = (e == 0) ? Wf : (e == 1) ? Wi : (e == 2) ? Wo : Wc;
        const float* U = (e == 0) ? Uf : (e == 1) ? Ui : (e == 2) ? Uo : Uc;
        g_Wp[i] = W[k * HH + j];
        g_Up[i] = U[k * HH + j];
        if (k == 0) {
            const float* B = (e == 0) ? bf : (e == 1) ? bi : (e == 2) ? bo : bc;
            g_bp[p] = B[j];
        }
    }
}

// ---------------- phase 1: xg[s*64+b][pcol] = x[b][s][:] @ Wp + bias ----------------
__global__ __launch_bounds__(256) void xproj_kernel(const float* __restrict__ x)
{
    __shared__ float As[8][132];   // [k][m], padded
    __shared__ float Bs[8][128];   // [k][n]
    int t  = threadIdx.x;
    int m0 = blockIdx.x * 128;
    int n0 = blockIdx.y * 128;
    int tm = t >> 4, tn = t & 15;

    int arow = t >> 1;
    int akq  = (t & 1) * 4;
    int gm = m0 + arow;
    int bb = gm & 63, ss = gm >> 6;
    const float* aptr = x + ((size_t)bb * SQ + ss) * HH + akq;

    int bkk = t >> 5;
    int bnq = (t & 31) * 4;
    const float* bptr = g_Wp + (size_t)bkk * GC + n0 + bnq;

    ull acc[8][4];
#pragma unroll
    for (int i = 0; i < 8; i++)
#pragma unroll
        for (int j = 0; j < 4; j++) acc[i][j] = 0ull;

    for (int k0 = 0; k0 < HH; k0 += 8) {
        float4 av = *(const float4*)(aptr + k0);
        float4 bv = *(const float4*)(bptr + (size_t)k0 * GC);
        __syncthreads();
        As[akq + 0][arow] = av.x;
        As[akq + 1][arow] = av.y;
        As[akq + 2][arow] = av.z;
        As[akq + 3][arow] = av.w;
        *(float4*)&Bs[bkk][bnq] = bv;
        __syncthreads();
#pragma unroll
        for (int kk = 0; kk < 8; kk++) {
            F4U2 b0, b1;
            float4 a0 = *(const float4*)&As[kk][tm * 8];
            float4 a1 = *(const float4*)&As[kk][tm * 8 + 4];
            b0.f4 = *(const float4*)&Bs[kk][tn * 8];
            b1.f4 = *(const float4*)&Bs[kk][tn * 8 + 4];
            ull bp_[4] = { b0.u2.x, b0.u2.y, b1.u2.x, b1.u2.y };
            float aa[8] = { a0.x, a0.y, a0.z, a0.w, a1.x, a1.y, a1.z, a1.w };
#pragma unroll
            for (int i = 0; i < 8; i++) {
                ull ad = pk2(aa[i], aa[i]);
#pragma unroll
                for (int j = 0; j < 4; j++) fma2(acc[i][j], ad, bp_[j]);
            }
        }
    }

    float4 bi0 = *(const float4*)(g_bp + n0 + tn * 8);
    float4 bi1 = *(const float4*)(g_bp + n0 + tn * 8 + 4);
#pragma unroll
    for (int i = 0; i < 8; i++) {
        float2 v0 = unpk(acc[i][0]), v1 = unpk(acc[i][1]);
        float2 v2 = unpk(acc[i][2]), v3 = unpk(acc[i][3]);
        float* o = g_xg + (size_t)(m0 + tm * 8 + i) * GC + n0 + tn * 8;
        float4 w0 = { v0.x + bi0.x, v0.y + bi0.y, v1.x + bi0.z, v1.y + bi0.w };
        float4 w1 = { v2.x + bi1.x, v2.y + bi1.y, v3.x + bi1.z, v3.y + bi1.w };
        *(float4*)o = w0;
        *(float4*)(o + 4) = w1;
    }
}

// ---------------- phase 2: persistent recurrence, 16 clusters x 8 CTAs ----------------
// Cluster = one batch group (4 batches). CTA r owns 128 gate-cols (32 hidden units).
// U slice lives in REGISTERS (64 f32x2 per thread). h exchanged via DSMEM stores into
// all 8 peers' double-buffered smH + split cluster barrier.
__global__ void __cluster_dims__(8, 1, 1) __launch_bounds__(256, 1) rnn_kernel()
{
    __shared__ float smH[2][HH * 4];     // [buf][k*4 + b]   4KB each
    __shared__ float smR[8][4][128];     // [ksplit][batch][col] 16KB

    int t   = threadIdx.x;
    int grp = blockIdx.x >> 3;
    int r   = blockIdx.x & 7;
    int b0  = grp * 4;
    int c0  = r * 128;

    int ks = t >> 5;          // 8 k-splits of 32
    int cq = t & 31;          // col quad: cols c0 + 4cq .. +3
    int eb = t >> 5, ecq = t & 31;   // epilogue map (t<128): batch eb, unit quad ecq

    // Load U block into registers, pre-packed as f32x2 col-pairs.
    ull u0[32], u1[32];
#pragma unroll
    for (int k = 0; k < 32; k++) {
        int kg = ks * 32 + k;
        F4U2 v; v.f4 = __ldg((const float4*)(g_Up + (size_t)kg * GC + c0 + 4 * cq));
        u0[k] = v.u2.x;
        u1[k] = v.u2.y;
    }

    // zero h buffer 0
    for (int i = t; i < HH * 4; i += 256) smH[0][i] = 0.0f;
    __syncthreads();

    uint32_t smH_base = (uint32_t)__cvta_generic_to_shared(&smH[0][0]);
    uint32_t myslot   = (uint32_t)(((r * 32 + ecq) * 4 + eb) * 4);  // byte off within a buf
    float C = 0.0f;

    asm volatile("barrier.cluster.arrive.aligned;" ::: "memory");

    int p = 0;
    for (int s = 0; s < SQ; s++) {
        // prefetch xg for this step BEFORE the cluster wait (hides DRAM latency)
        float4 xg4 = make_float4(0.f, 0.f, 0.f, 0.f);
        if (t < 128)
            xg4 = __ldcs((const float4*)(g_xg + ((size_t)s * NB + b0 + eb) * GC + c0 + 4 * ecq));

        asm volatile("barrier.cluster.wait.aligned;" ::: "memory");

        // GEMM partials: g[b][cols] += sum_{k in split} h[b][k] * U[k][cols]
        ull a00 = 0, a01 = 0, a10 = 0, a11 = 0, a20 = 0, a21 = 0, a30 = 0, a31 = 0;
        const float4* H4 = (const float4*)&smH[p][0];
#pragma unroll
        for (int k = 0; k < 32; k++) {
            float4 hv = H4[ks * 32 + k];          // broadcast LDS (free crossbar)
            ull h0 = pk2(hv.x, hv.x), h1 = pk2(hv.y, hv.y);
            ull h2 = pk2(hv.z, hv.z), h3 = pk2(hv.w, hv.w);
            fma2(a00, h0, u0[k]); fma2(a01, h0, u1[k]);
            fma2(a10, h1, u0[k]); fma2(a11, h1, u1[k]);
            fma2(a20, h2, u0[k]); fma2(a21, h2, u1[k]);
            fma2(a30, h3, u0[k]); fma2(a31, h3, u1[k]);
        }
        {
            float2 x0, x1;
            x0 = unpk(a00); x1 = unpk(a01); *(float4*)&smR[ks][0][4 * cq] = make_float4(x0.x, x0.y, x1.x, x1.y);
            x0 = unpk(a10); x1 = unpk(a11); *(float4*)&smR[ks][1][4 * cq] = make_float4(x0.x, x0.y, x1.x, x1.y);
            x0 = unpk(a20); x1 = unpk(a21); *(float4*)&smR[ks][2][4 * cq] = make_float4(x0.x, x0.y, x1.x, x1.y);
            x0 = unpk(a30); x1 = unpk(a31); *(float4*)&smR[ks][3][4 * cq] = make_float4(x0.x, x0.y, x1.x, x1.y);
        }
        __syncthreads();

        // reduce + gates + state update + DSMEM broadcast of new h
        if (t < 128) {
            float4 g4 = xg4;
#pragma unroll
            for (int q = 0; q < 8; q++) {
                float4 pv = *(const float4*)&smR[q][eb][4 * ecq];
                g4.x += pv.x; g4.y += pv.y; g4.z += pv.z; g4.w += pv.w;
            }
            float fg = 1.0f / (1.0f + __expf(-g4.x));
            float ig = 1.0f / (1.0f + __expf(-g4.y));
            float og = 1.0f / (1.0f + __expf(-g4.z));
            float cc = 1.0f / (1.0f + __expf(-g4.w));   // candidate uses sigmoid (per reference)
            C = fg * C + ig * cc;
            float h = og * tanhf(C);

            uint32_t dst = smH_base + (uint32_t)((p ^ 1) * HH * 4 * 4) + myslot;
#pragma unroll
            for (int pr = 0; pr < 8; pr++) {
                uint32_t ra;
                asm("mapa.shared::cluster.u32 %0, %1, %2;" : "=r"(ra) : "r"(dst), "r"(pr));
                asm volatile("st.shared::cluster.f32 [%0], %1;" :: "r"(ra), "f"(h));
            }
            if (s == SQ - 1)
                g_hT[(b0 + eb) * HH + r * 32 + ecq] = h;
        }
        // arrive releases the DSMEM stores; epilogue readers of smR have finished
        // before arriving, so next step's partial stores cannot race.
        asm volatile("barrier.cluster.arrive.aligned;" ::: "memory");
        p ^= 1;
    }
    asm volatile("barrier.cluster.wait.aligned;" ::: "memory");
}

// ---------------- phase 3: out = h_T @ Why + bias_y ----------------
__global__ __launch_bounds__(256) void out_kernel(const float* __restrict__ Why,
                                                  const float* __restrict__ by,
                                                  float* __restrict__ out)
{
    __shared__ float hs[HH];
    int b = blockIdx.x, n = threadIdx.x;
    hs[n] = g_hT[b * HH + n];
    __syncthreads();
    float acc = by[n];
    for (int k = 0; k < HH; k++)
        acc = fmaf(hs[k], Why[(size_t)k * HH + n], acc);
    out[b * HH + n] = acc;
}

// ---------------- launch ----------------
extern "C" void kernel_launch(void* const* d_in, const int* in_sizes, int n_in,
                              void* d_out, int out_size)
{
    (void)in_sizes; (void)n_in; (void)out_size;
    const float* x   = (const float*)d_in[0];
    const float* Wf  = (const float*)d_in[1];
    const float* Uf  = (const float*)d_in[2];
    const float* bf  = (const float*)d_in[3];
    const float* Wi  = (const float*)d_in[4];
    const float* Ui  = (const float*)d_in[5];
    const float* bi  = (const float*)d_in[6];
    const float* Wc  = (const float*)d_in[7];
    const float* Uc  = (const float*)d_in[8];
    const float* bc  = (const float*)d_in[9];
    const float* Wo  = (const float*)d_in[10];
    const float* Uo  = (const float*)d_in[11];
    const float* bo  = (const float*)d_in[12];
    const float* Why = (const float*)d_in[13];
    const float* by  = (const float*)d_in[14];
    float* out = (float*)d_out;

    pack_kernel<<<1024, 256>>>(Wf, Uf, bf, Wi, Ui, bi, Wc, Uc, bc, Wo, Uo, bo);

    dim3 g1(2048, 8);
    xproj_kernel<<<g1, 256>>>(x);

    rnn_kernel<<<128, 256>>>();

    out_kernel<<<64, 256>>>(Why, by, out);
}

// round 6
// speedup vs baseline: 1.1264x; 1.1264x over previous
#include <cuda_runtime.h>
#include <cstdint>
#include <cstddef>

#define SQ 4096
#define NB 64
#define HH 256
#define GC 1024   // 4 gates * 256 units, packed: pcol = j*4 + e  (e: 0=f,1=i,2=o,3=c)

typedef unsigned long long ull;

// ---------------- static device scratch (no allocations allowed) ----------------
__device__ float g_xg[(size_t)SQ * NB * GC];   // 1 GB input projections (+bias)
__device__ float g_Wp[HH * GC];                // packed W_all [k][pcol]
__device__ float g_Up[HH * GC];                // packed U_all [k][pcol]
__device__ float g_bp[GC];                     // packed bias
__device__ float g_hT[NB * HH];                // final hidden state

// ---------------- f32x2 helpers ----------------
__device__ __forceinline__ ull pk2(float x, float y) {
    ull r; asm("mov.b64 %0, {%1, %2};" : "=l"(r) : "f"(x), "f"(y)); return r;
}
__device__ __forceinline__ void fma2(ull& d, ull a, ull b) {
    asm("fma.rn.f32x2 %0, %1, %2, %0;" : "+l"(d) : "l"(a), "l"(b));
}
__device__ __forceinline__ float2 unpk(ull v) {
    float2 r; asm("mov.b64 {%0, %1}, %2;" : "=f"(r.x), "=f"(r.y) : "l"(v)); return r;
}
union F4U2 { float4 f4; ulonglong2 u2; };

// ---------------- phase 0: pack weights ----------------
__global__ void pack_kernel(const float* __restrict__ Wf, const float* __restrict__ Uf, const float* __restrict__ bf,
                            const float* __restrict__ Wi, const float* __restrict__ Ui, const float* __restrict__ bi,
                            const float* __restrict__ Wc, const float* __restrict__ Uc, const float* __restrict__ bc,
                            const float* __restrict__ Wo, const float* __restrict__ Uo, const float* __restrict__ bo)
{
    int i = blockIdx.x * blockDim.x + threadIdx.x;   // 0 .. 262143
    if (i < HH * GC) {
        int k = i >> 10, p = i & 1023;
        int j = p >> 2, e = p & 3;                   // e: 0=f,1=i,2=o,3=c
        const float* W = (e == 0) ? Wf : (e == 1) ? Wi : (e == 2) ? Wo : Wc;
        const float* U = (e == 0) ? Uf : (e == 1) ? Ui : (e == 2) ? Uo : Uc;
        g_Wp[i] = W[k * HH + j];
        g_Up[i] = U[k * HH + j];
        if (k == 0) {
            const float* B = (e == 0) ? bf : (e == 1) ? bi : (e == 2) ? bo : bc;
            g_bp[p] = B[j];
        }
    }
}

// ---------------- phase 1: xg[s*64+b][pcol] = x[b][s][:] @ Wp + bias ----------------
__global__ __launch_bounds__(256) void xproj_kernel(const float* __restrict__ x)
{
    __shared__ float As[8][132];   // [k][m], padded
    __shared__ float Bs[8][128];   // [k][n]
    int t  = threadIdx.x;
    int m0 = blockIdx.x * 128;
    int n0 = blockIdx.y * 128;
    int tm = t >> 4, tn = t & 15;

    int arow = t >> 1;
    int akq  = (t & 1) * 4;
    int gm = m0 + arow;
    int bb = gm & 63, ss = gm >> 6;
    const float* aptr = x + ((size_t)bb * SQ + ss) * HH + akq;

    int bkk = t >> 5;
    int bnq = (t & 31) * 4;
    const float* bptr = g_Wp + (size_t)bkk * GC + n0 + bnq;

    ull acc[8][4];
#pragma unroll
    for (int i = 0; i < 8; i++)
#pragma unroll
        for (int j = 0; j < 4; j++) acc[i][j] = 0ull;

    for (int k0 = 0; k0 < HH; k0 += 8) {
        float4 av = *(const float4*)(aptr + k0);
        float4 bv = *(const float4*)(bptr + (size_t)k0 * GC);
        __syncthreads();
        As[akq + 0][arow] = av.x;
        As[akq + 1][arow] = av.y;
        As[akq + 2][arow] = av.z;
        As[akq + 3][arow] = av.w;
        *(float4*)&Bs[bkk][bnq] = bv;
        __syncthreads();
#pragma unroll
        for (int kk = 0; kk < 8; kk++) {
            F4U2 b0, b1;
            float4 a0 = *(const float4*)&As[kk][tm * 8];
            float4 a1 = *(const float4*)&As[kk][tm * 8 + 4];
            b0.f4 = *(const float4*)&Bs[kk][tn * 8];
            b1.f4 = *(const float4*)&Bs[kk][tn * 8 + 4];
            ull bp_[4] = { b0.u2.x, b0.u2.y, b1.u2.x, b1.u2.y };
            float aa[8] = { a0.x, a0.y, a0.z, a0.w, a1.x, a1.y, a1.z, a1.w };
#pragma unroll
            for (int i = 0; i < 8; i++) {
                ull ad = pk2(aa[i], aa[i]);
#pragma unroll
                for (int j = 0; j < 4; j++) fma2(acc[i][j], ad, bp_[j]);
            }
        }
    }

    float4 bi0 = *(const float4*)(g_bp + n0 + tn * 8);
    float4 bi1 = *(const float4*)(g_bp + n0 + tn * 8 + 4);
#pragma unroll
    for (int i = 0; i < 8; i++) {
        float2 v0 = unpk(acc[i][0]), v1 = unpk(acc[i][1]);
        float2 v2 = unpk(acc[i][2]), v3 = unpk(acc[i][3]);
        float* o = g_xg + (size_t)(m0 + tm * 8 + i) * GC + n0 + tn * 8;
        float4 w0 = { v0.x + bi0.x, v0.y + bi0.y, v1.x + bi0.z, v1.y + bi0.w };
        float4 w1 = { v2.x + bi1.x, v2.y + bi1.y, v3.x + bi1.z, v3.y + bi1.w };
        *(float4*)o = w0;
        *(float4*)(o + 4) = w1;
    }
}

// ---------------- phase 2: persistent recurrence, 16 clusters x 8 CTAs ----------------
// Cluster = one batch group (4 batches). CTA r owns 128 gate-cols (32 hidden units).
// h exchanged as pre-duplicated f32x2 pairs via st.async into every peer's smH2,
// completion via per-buffer mbarrier (expect_tx = 8 CTAs * 128 thr * 8B = 8192B).
__global__ void __cluster_dims__(8, 1, 1) __launch_bounds__(256, 1) rnn_kernel()
{
    extern __shared__ float smU[];          // [256][128]  128KB (dynamic)
    __shared__ ull  smH2[2][HH * 4];        // [buf][k*4 + b] duplicated pairs, 2x8KB
    __shared__ float smR[8][4][128];        // [ksplit][batch][col] 16KB
    __shared__ ull  bars[2];                // mbarrier per h-buffer

    int t   = threadIdx.x;
    int grp = blockIdx.x >> 3;
    int r   = blockIdx.x & 7;
    int b0  = grp * 4;
    int c0  = r * 128;

    int ks = t >> 5;                 // 8 k-splits of 32
    int cg = t & 31;                 // col quad: cols c0 + 4cg .. +3
    int eb = t >> 5, ecq = t & 31;   // epilogue map (t<128): batch eb, unit quad ecq

    // fill smU (full U slice, k-major rows of 128 cols)
    {
        float4* dst = (float4*)smU;
        for (int q = t; q < HH * 32; q += 256) {
            int k = q >> 5, cq = q & 31;
            dst[q] = *(const float4*)(g_Up + (size_t)k * GC + c0 + cq * 4);
        }
    }
    // first 16 k-rows of this thread's split live in registers (pre-packed col pairs)
    ull ur0[16], ur1[16];
#pragma unroll
    for (int kk = 0; kk < 16; kk++) {
        int kg = ks * 32 + kk;
        F4U2 v; v.f4 = __ldg((const float4*)(g_Up + (size_t)kg * GC + c0 + 4 * cg));
        ur0[kk] = v.u2.x;
        ur1[kk] = v.u2.y;
    }

    // zero h buffer 0 (step 0 reads zeros)
    for (int i = t; i < HH * 4; i += 256) smH2[0][i] = 0ull;

    uint32_t bar0 = (uint32_t)__cvta_generic_to_shared(&bars[0]);
    uint32_t bar1 = (uint32_t)__cvta_generic_to_shared(&bars[1]);
    uint32_t h2b  = (uint32_t)__cvta_generic_to_shared(&smH2[0][0]);

    if (t == 0) {
        asm volatile("mbarrier.init.shared.b64 [%0], 1;" :: "r"(bar0) : "memory");
        asm volatile("mbarrier.init.shared.b64 [%0], 1;" :: "r"(bar1) : "memory");
        // pre-arm: bar1 receives step-0 epilogue (for step 1), bar0 step-1 epilogue (for step 2)
        asm volatile("mbarrier.arrive.expect_tx.shared.b64 _, [%0], 8192;" :: "r"(bar1) : "memory");
        asm volatile("mbarrier.arrive.expect_tx.shared.b64 _, [%0], 8192;" :: "r"(bar0) : "memory");
    }
    __syncthreads();
    // all mbarriers + smH2 zeros visible cluster-wide before any st.async
    asm volatile("barrier.cluster.arrive.aligned;" ::: "memory");
    asm volatile("barrier.cluster.wait.aligned;" ::: "memory");

    float C = 0.0f;
    int ph0 = 0, ph1 = 0;
    uint32_t myslot = (uint32_t)(((r * 32 + ecq) * 4 + eb) * 8);   // byte off within a buffer

    for (int s = 0; s < SQ; s++) {
        int p = s & 1;

        // prefetch xg for this step before blocking on peers
        float4 xg4 = make_float4(0.f, 0.f, 0.f, 0.f);
        if (t < 128)
            xg4 = __ldcs((const float4*)(g_xg + ((size_t)s * NB + b0 + eb) * GC + c0 + 4 * ecq));

        if (s > 0) {
            uint32_t bp = p ? bar1 : bar0;
            int phv = p ? ph1 : ph0;
            uint32_t done;
            asm volatile(
                "{\n\t.reg .pred P;\n\t"
                "mbarrier.try_wait.parity.acquire.cta.shared::cta.b64 P, [%1], %2;\n\t"
                "selp.b32 %0, 1, 0, P;\n\t}"
                : "=r"(done) : "r"(bp), "r"(phv) : "memory");
            if (!done) {
                asm volatile(
                    "{\n\t.reg .pred P;\n"
                    "W_%=:\n\t"
                    "mbarrier.try_wait.parity.acquire.cta.shared::cta.b64 P, [%0], %1, 0x989680;\n\t"
                    "@P bra.uni D_%=;\n\t"
                    "bra.uni W_%=;\n"
                    "D_%=:\n\t}"
                    :: "r"(bp), "r"(phv) : "memory");
            }
            if (p) ph1 ^= 1; else ph0 ^= 1;
            // re-arm this barrier for step s+2 (safe: peers' next tx are gated by our sends below)
            if (t == 0)
                asm volatile("mbarrier.arrive.expect_tx.shared.b64 _, [%0], 8192;" :: "r"(bp) : "memory");
        }

        // GEMM partials: g[b][cols] += sum_{k in split} h[b][k] * U[k][cols]
        ull a00 = 0, a01 = 0, a10 = 0, a11 = 0, a20 = 0, a21 = 0, a30 = 0, a31 = 0;
        const ull* H = &smH2[p][0];
        int kb = ks * 32;
#pragma unroll
        for (int kk = 0; kk < 16; kk++) {
            ulonglong2 hA = *(const ulonglong2*)&H[(kb + kk) * 4];
            ulonglong2 hB = *(const ulonglong2*)&H[(kb + kk) * 4 + 2];
            fma2(a00, hA.x, ur0[kk]); fma2(a01, hA.x, ur1[kk]);
            fma2(a10, hA.y, ur0[kk]); fma2(a11, hA.y, ur1[kk]);
            fma2(a20, hB.x, ur0[kk]); fma2(a21, hB.x, ur1[kk]);
            fma2(a30, hB.y, ur0[kk]); fma2(a31, hB.y, ur1[kk]);
        }
#pragma unroll
        for (int kk = 16; kk < 32; kk++) {
            int k = kb + kk;
            F4U2 u; u.f4 = *(const float4*)&smU[k * 128 + 4 * cg];
            ulonglong2 hA = *(const ulonglong2*)&H[k * 4];
            ulonglong2 hB = *(const ulonglong2*)&H[k * 4 + 2];
            fma2(a00, hA.x, u.u2.x); fma2(a01, hA.x, u.u2.y);
            fma2(a10, hA.y, u.u2.x); fma2(a11, hA.y, u.u2.y);
            fma2(a20, hB.x, u.u2.x); fma2(a21, hB.x, u.u2.y);
            fma2(a30, hB.y, u.u2.x); fma2(a31, hB.y, u.u2.y);
        }
        {
            float2 x0, x1;
            x0 = unpk(a00); x1 = unpk(a01); *(float4*)&smR[ks][0][4 * cg] = make_float4(x0.x, x0.y, x1.x, x1.y);
            x0 = unpk(a10); x1 = unpk(a11); *(float4*)&smR[ks][1][4 * cg] = make_float4(x0.x, x0.y, x1.x, x1.y);
            x0 = unpk(a20); x1 = unpk(a21); *(float4*)&smR[ks][2][4 * cg] = make_float4(x0.x, x0.y, x1.x, x1.y);
            x0 = unpk(a30); x1 = unpk(a31); *(float4*)&smR[ks][3][4 * cg] = make_float4(x0.x, x0.y, x1.x, x1.y);
        }
        __syncthreads();

        // reduce + gates + state update + DSMEM broadcast of new h (pre-duplicated)
        if (t < 128) {
            float4 g4 = xg4;
#pragma unroll
            for (int q = 0; q < 8; q++) {
                float4 pv = *(const float4*)&smR[q][eb][4 * ecq];
                g4.x += pv.x; g4.y += pv.y; g4.z += pv.z; g4.w += pv.w;
            }
            float fg = 1.0f / (1.0f + __expf(-g4.x));
            float ig = 1.0f / (1.0f + __expf(-g4.y));
            float og = 1.0f / (1.0f + __expf(-g4.z));
            float cc = 1.0f / (1.0f + __expf(-g4.w));   // candidate uses sigmoid (per reference)
            C = fg * C + ig * cc;
            float h = og * tanhf(C);

            if (s < SQ - 1) {
                ull hh = pk2(h, h);
                int pn = (s + 1) & 1;
                uint32_t dslot = h2b + (uint32_t)(pn * (HH * 4 * 8)) + myslot;
                uint32_t bsl   = pn ? bar1 : bar0;
#pragma unroll
                for (int pr = 0; pr < 8; pr++) {
                    uint32_t ra, rb;
                    asm("mapa.shared::cluster.u32 %0, %1, %2;" : "=r"(ra) : "r"(dslot), "r"(pr));
                    asm("mapa.shared::cluster.u32 %0, %1, %2;" : "=r"(rb) : "r"(bsl), "r"(pr));
                    asm volatile(
                        "st.async.weak.shared::cluster.mbarrier::complete_tx::bytes.b64 [%0], %1, [%2];"
                        :: "r"(ra), "l"(hh), "r"(rb) : "memory");
                }
            } else {
                g_hT[(b0 + eb) * HH + r * 32 + ecq] = h;
            }
        }
        __syncthreads();   // smR reuse safety for next step
    }
    // no in-flight async stores (last step sends nothing); plain exit
}

// ---------------- phase 3: out = h_T @ Why + bias_y ----------------
__global__ __launch_bounds__(256) void out_kernel(const float* __restrict__ Why,
                                                  const float* __restrict__ by,
                                                  float* __restrict__ out)
{
    __shared__ float hs[HH];
    int b = blockIdx.x, n = threadIdx.x;
    hs[n] = g_hT[b * HH + n];
    __syncthreads();
    float acc = by[n];
    for (int k = 0; k < HH; k++)
        acc = fmaf(hs[k], Why[(size_t)k * HH + n], acc);
    out[b * HH + n] = acc;
}

// ---------------- launch ----------------
extern "C" void kernel_launch(void* const* d_in, const int* in_sizes, int n_in,
                              void* d_out, int out_size)
{
    (void)in_sizes; (void)n_in; (void)out_size;
    const float* x   = (const float*)d_in[0];
    const float* Wf  = (const float*)d_in[1];
    const float* Uf  = (const float*)d_in[2];
    const float* bf  = (const float*)d_in[3];
    const float* Wi  = (const float*)d_in[4];
    const float* Ui  = (const float*)d_in[5];
    const float* bi  = (const float*)d_in[6];
    const float* Wc  = (const float*)d_in[7];
    const float* Uc  = (const float*)d_in[8];
    const float* bc  = (const float*)d_in[9];
    const float* Wo  = (const float*)d_in[10];
    const float* Uo  = (const float*)d_in[11];
    const float* bo  = (const float*)d_in[12];
    const float* Why = (const float*)d_in[13];
    const float* by  = (const float*)d_in[14];
    float* out = (float*)d_out;

    pack_kernel<<<1024, 256>>>(Wf, Uf, bf, Wi, Ui, bi, Wc, Uc, bc, Wo, Uo, bo);

    dim3 g1(2048, 8);
    xproj_kernel<<<g1, 256>>>(x);

    int smem = HH * 128 * (int)sizeof(float);   // 128KB dynamic (smU)
    cudaFuncSetAttribute(rnn_kernel, cudaFuncAttributeMaxDynamicSharedMemorySize, smem);
    rnn_kernel<<<128, 256, smem>>>();

    out_kernel<<<64, 256>>>(Why, by, out);
}

// round 7
// speedup vs baseline: 1.3318x; 1.1823x over previous
#include <cuda_runtime.h>
#include <cstdint>
#include <cstddef>

#define SQ 4096
#define NB 64
#define HH 256
#define GC 1024   // 4 gates * 256 units, packed: pcol = j*4 + e  (e: 0=f,1=i,2=o,3=c)

#define CANARY 0x7FBADBADu   // NaN payload; h = sig*tanh can never be NaN

typedef unsigned long long ull;

// ---------------- static device scratch (no allocations allowed) ----------------
__device__ float g_xg[(size_t)SQ * NB * GC];     // 1 GB input projections (+bias)
__device__ float g_Wp[HH * GC];                  // packed W_all [k][pcol]
__device__ float g_Up[HH * GC];                  // packed U_all [k][pcol]
__device__ float g_bp[GC];                       // packed bias
__device__ float g_hT[NB * HH];                  // final hidden state
__device__ unsigned g_hx[4][16][4][HH];          // h exchange ring [buf][grp][batch][k], 64KB

// ---------------- f32x2 helpers ----------------
__device__ __forceinline__ ull pk2(float x, float y) {
    ull r; asm("mov.b64 %0, {%1, %2};" : "=l"(r) : "f"(x), "f"(y)); return r;
}
__device__ __forceinline__ void fma2(ull& d, ull a, ull b) {
    asm("fma.rn.f32x2 %0, %1, %2, %0;" : "+l"(d) : "l"(a), "l"(b));
}
__device__ __forceinline__ float2 unpk(ull v) {
    float2 r; asm("mov.b64 {%0, %1}, %2;" : "=f"(r.x), "=f"(r.y) : "l"(v)); return r;
}
union F4U2 { float4 f4; ulonglong2 u2; };

__device__ __forceinline__ unsigned ldacq(const unsigned* p) {
    unsigned v; asm volatile("ld.acquire.gpu.u32 %0, [%1];" : "=r"(v) : "l"(p) : "memory"); return v;
}
__device__ __forceinline__ void strel(unsigned* p, unsigned v) {
    asm volatile("st.release.gpu.u32 [%0], %1;" :: "l"(p), "r"(v) : "memory");
}
__device__ __forceinline__ float fsig(float x) {   // 1/(1+e^-x) via fast exp
    return 1.0f / (1.0f + __expf(-x));
}
__device__ __forceinline__ float ftanh(float x) {  // 1 - 2/(e^2x+1)
    return 1.0f - 2.0f / (__expf(2.0f * x) + 1.0f);
}

// ---------------- phase 0: pack weights + poison exchange ring ----------------
__global__ void pack_kernel(const float* __restrict__ Wf, const float* __restrict__ Uf, const float* __restrict__ bf,
                            const float* __restrict__ Wi, const float* __restrict__ Ui, const float* __restrict__ bi,
                            const float* __restrict__ Wc, const float* __restrict__ Uc, const float* __restrict__ bc,
                            const float* __restrict__ Wo, const float* __restrict__ Uo, const float* __restrict__ bo)
{
    int i = blockIdx.x * blockDim.x + threadIdx.x;   // 0 .. 262143
    if (i < HH * GC) {
        int k = i >> 10, p = i & 1023;
        int j = p >> 2, e = p & 3;                   // e: 0=f,1=i,2=o,3=c
        const float* W = (e == 0) ? Wf : (e == 1) ? Wi : (e == 2) ? Wo : Wc;
        const float* U = (e == 0) ? Uf : (e == 1) ? Ui : (e == 2) ? Uo : Uc;
        g_Wp[i] = W[k * HH + j];
        g_Up[i] = U[k * HH + j];
        if (k == 0) {
            const float* B = (e == 0) ? bf : (e == 1) ? bi : (e == 2) ? bo : bc;
            g_bp[p] = B[j];
        }
    }
    if (i < 4 * 16 * 4 * HH) ((unsigned*)g_hx)[i] = CANARY;
}

// ---------------- phase 1: xg[s*64+b][pcol] = x[b][s][:] @ Wp + bias ----------------
__global__ __launch_bounds__(256) void xproj_kernel(const float* __restrict__ x)
{
    __shared__ float As[8][132];   // [k][m], padded
    __shared__ float Bs[8][128];   // [k][n]
    int t  = threadIdx.x;
    int m0 = blockIdx.x * 128;
    int n0 = blockIdx.y * 128;
    int tm = t >> 4, tn = t & 15;

    int arow = t >> 1;
    int akq  = (t & 1) * 4;
    int gm = m0 + arow;
    int bb = gm & 63, ss = gm >> 6;
    const float* aptr = x + ((size_t)bb * SQ + ss) * HH + akq;

    int bkk = t >> 5;
    int bnq = (t & 31) * 4;
    const float* bptr = g_Wp + (size_t)bkk * GC + n0 + bnq;

    ull acc[8][4];
#pragma unroll
    for (int i = 0; i < 8; i++)
#pragma unroll
        for (int j = 0; j < 4; j++) acc[i][j] = 0ull;

    for (int k0 = 0; k0 < HH; k0 += 8) {
        float4 av = *(const float4*)(aptr + k0);
        float4 bv = *(const float4*)(bptr + (size_t)k0 * GC);
        __syncthreads();
        As[akq + 0][arow] = av.x;
        As[akq + 1][arow] = av.y;
        As[akq + 2][arow] = av.z;
        As[akq + 3][arow] = av.w;
        *(float4*)&Bs[bkk][bnq] = bv;
        __syncthreads();
#pragma unroll
        for (int kk = 0; kk < 8; kk++) {
            F4U2 b0, b1;
            float4 a0 = *(const float4*)&As[kk][tm * 8];
            float4 a1 = *(const float4*)&As[kk][tm * 8 + 4];
            b0.f4 = *(const float4*)&Bs[kk][tn * 8];
            b1.f4 = *(const float4*)&Bs[kk][tn * 8 + 4];
            ull bp_[4] = { b0.u2.x, b0.u2.y, b1.u2.x, b1.u2.y };
            float aa[8] = { a0.x, a0.y, a0.z, a0.w, a1.x, a1.y, a1.z, a1.w };
#pragma unroll
            for (int i = 0; i < 8; i++) {
                ull ad = pk2(aa[i], aa[i]);
#pragma unroll
                for (int j = 0; j < 4; j++) fma2(acc[i][j], ad, bp_[j]);
            }
        }
    }

    float4 bi0 = *(const float4*)(g_bp + n0 + tn * 8);
    float4 bi1 = *(const float4*)(g_bp + n0 + tn * 8 + 4);
#pragma unroll
    for (int i = 0; i < 8; i++) {
        float2 v0 = unpk(acc[i][0]), v1 = unpk(acc[i][1]);
        float2 v2 = unpk(acc[i][2]), v3 = unpk(acc[i][3]);
        float* o = g_xg + (size_t)(m0 + tm * 8 + i) * GC + n0 + tn * 8;
        float4 w0 = { v0.x + bi0.x, v0.y + bi0.y, v1.x + bi0.z, v1.y + bi0.w };
        float4 w1 = { v2.x + bi1.x, v2.y + bi1.y, v3.x + bi1.z, v3.y + bi1.w };
        *(float4*)o = w0;
        *(float4*)(o + 4) = w1;
    }
}

// ---------------- phase 2: persistent recurrence, canary-poll exchange ----------------
// 128 CTAs = 16 groups (4 batches) x 8 col-CTAs (128 gate-cols = 32 units).
// h handoff: producer re-poisons buf(s+2) slot then st.release h into buf(s+1);
// consumers ld.acquire-poll until != CANARY. No fences/atomics/barriers.
__global__ __launch_bounds__(256, 1) void rnn_kernel()
{
    extern __shared__ float smU[];        // [8 ks][16 rows (kk=16..31)][128 cols] = 64KB
    __shared__ ull  smH2[HH * 4];         // duplicated pairs [k*4 + b], 8KB
    __shared__ float smR[8][4][128];      // [ksplit][batch][col] 16KB

    int t   = threadIdx.x;
    int grp = blockIdx.x >> 3;
    int r   = blockIdx.x & 7;
    int c0  = r * 128;

    int ks = t >> 5;                 // 8 k-splits of 32
    int cg = t & 31;                 // col quad within CTA slice
    int eb = t >> 5, ecq = t & 31;   // epilogue map (t<128): batch eb, unit quad ecq

    // smU: only the rows the smem half of the GEMM reads (kk = 16..31 of each split)
    {
        float4* dst = (float4*)smU;
        for (int q = t; q < 128 * 32; q += 256) {
            int row = q >> 5, cq4 = q & 31;
            int ks2 = row >> 4, j = row & 15;
            int kg = ks2 * 32 + 16 + j;
            dst[q] = *(const float4*)(g_Up + (size_t)kg * GC + c0 + cq4 * 4);
        }
    }
    // register half: rows kk = 0..15 of this thread's split, pre-packed col pairs
    ull ur0[16], ur1[16];
#pragma unroll
    for (int kk = 0; kk < 16; kk++) {
        int kg = ks * 32 + kk;
        F4U2 v; v.f4 = __ldg((const float4*)(g_Up + (size_t)kg * GC + c0 + 4 * cg));
        ur0[kk] = v.u2.x;
        ur1[kk] = v.u2.y;
    }

    // step 0 consumes h = 0
    for (int i = t; i < HH * 4; i += 256) smH2[i] = 0ull;

    float C = 0.0f;

    for (int s = 0; s < SQ; s++) {
        // prefetch xg before blocking on peers (hides DRAM latency behind the poll)
        float4 xg4 = make_float4(0.f, 0.f, 0.f, 0.f);
        if (t < 128)
            xg4 = __ldcs((const float4*)(g_xg + ((size_t)s * NB + grp * 4 + eb) * GC + c0 + 4 * ecq));

        if (s > 0) {
            int buf = s & 3;
            const unsigned* slot = &g_hx[buf][grp][0][t];
            unsigned v0, v1, v2, v3;
            do {
                v0 = ldacq(slot + 0 * HH);
                v1 = ldacq(slot + 1 * HH);
                v2 = ldacq(slot + 2 * HH);
                v3 = ldacq(slot + 3 * HH);
            } while (v0 == CANARY || v1 == CANARY || v2 == CANARY || v3 == CANARY);
            float h0 = __uint_as_float(v0), h1 = __uint_as_float(v1);
            float h2 = __uint_as_float(v2), h3 = __uint_as_float(v3);
            ulonglong2 A, B;
            A.x = pk2(h0, h0); A.y = pk2(h1, h1);
            B.x = pk2(h2, h2); B.y = pk2(h3, h3);
            *(ulonglong2*)&smH2[t * 4]     = A;
            *(ulonglong2*)&smH2[t * 4 + 2] = B;
        }
        __syncthreads();

        // GEMM partials: g[b][cols] += sum_{k in split} h[b][k] * U[k][cols]
        ull a00 = 0, a01 = 0, a10 = 0, a11 = 0, a20 = 0, a21 = 0, a30 = 0, a31 = 0;
        const ull* H = smH2;
        int kb = ks * 32;
#pragma unroll
        for (int kk = 0; kk < 16; kk++) {
            ulonglong2 hA = *(const ulonglong2*)&H[(kb + kk) * 4];
            ulonglong2 hB = *(const ulonglong2*)&H[(kb + kk) * 4 + 2];
            fma2(a00, hA.x, ur0[kk]); fma2(a01, hA.x, ur1[kk]);
            fma2(a10, hA.y, ur0[kk]); fma2(a11, hA.y, ur1[kk]);
            fma2(a20, hB.x, ur0[kk]); fma2(a21, hB.x, ur1[kk]);
            fma2(a30, hB.y, ur0[kk]); fma2(a31, hB.y, ur1[kk]);
        }
#pragma unroll
        for (int kk = 0; kk < 16; kk++) {
            int k = kb + 16 + kk;
            F4U2 u; u.f4 = *(const float4*)&smU[((ks * 16 + kk) * 128) + 4 * cg];
            ulonglong2 hA = *(const ulonglong2*)&H[k * 4];
            ulonglong2 hB = *(const ulonglong2*)&H[k * 4 + 2];
            fma2(a00, hA.x, u.u2.x); fma2(a01, hA.x, u.u2.y);
            fma2(a10, hA.y, u.u2.x); fma2(a11, hA.y, u.u2.y);
            fma2(a20, hB.x, u.u2.x); fma2(a21, hB.x, u.u2.y);
            fma2(a30, hB.y, u.u2.x); fma2(a31, hB.y, u.u2.y);
        }
        {
            float2 x0, x1;
            x0 = unpk(a00); x1 = unpk(a01); *(float4*)&smR[ks][0][4 * cg] = make_float4(x0.x, x0.y, x1.x, x1.y);
            x0 = unpk(a10); x1 = unpk(a11); *(float4*)&smR[ks][1][4 * cg] = make_float4(x0.x, x0.y, x1.x, x1.y);
            x0 = unpk(a20); x1 = unpk(a21); *(float4*)&smR[ks][2][4 * cg] = make_float4(x0.x, x0.y, x1.x, x1.y);
            x0 = unpk(a30); x1 = unpk(a31); *(float4*)&smR[ks][3][4 * cg] = make_float4(x0.x, x0.y, x1.x, x1.y);
        }
        __syncthreads();

        // reduce + gates + state update + h publish
        if (t < 128) {
            float4 g4 = xg4;
#pragma unroll
            for (int q = 0; q < 8; q++) {
                float4 pv = *(const float4*)&smR[q][eb][4 * ecq];
                g4.x += pv.x; g4.y += pv.y; g4.z += pv.z; g4.w += pv.w;
            }
            float fg = fsig(g4.x);
            float ig = fsig(g4.y);
            float og = fsig(g4.z);
            float cc = fsig(g4.w);     // candidate uses sigmoid (per reference)
            C = fg * C + ig * cc;
            float h = og * ftanh(C);

            int unit = r * 32 + ecq;
            if (s < SQ - 1) {
                // re-poison the ring slot two steps ahead (weak), THEN release-publish h.
                // release makes the poison visible to anyone who acquires this h.
                g_hx[(s + 2) & 3][grp][eb][unit] = CANARY;
                strel(&g_hx[(s + 1) & 3][grp][eb][unit], __float_as_uint(h));
            } else {
                g_hT[(grp * 4 + eb) * HH + unit] = h;
            }
        }
    }
}

// ---------------- phase 3: out = h_T @ Why + bias_y ----------------
__global__ __launch_bounds__(256) void out_kernel(const float* __restrict__ Why,
                                                  const float* __restrict__ by,
                                                  float* __restrict__ out)
{
    __shared__ float hs[HH];
    int b = blockIdx.x, n = threadIdx.x;
    hs[n] = g_hT[b * HH + n];
    __syncthreads();
    float acc = by[n];
    for (int k = 0; k < HH; k++)
        acc = fmaf(hs[k], Why[(size_t)k * HH + n], acc);
    out[b * HH + n] = acc;
}

// ---------------- launch ----------------
extern "C" void kernel_launch(void* const* d_in, const int* in_sizes, int n_in,
                              void* d_out, int out_size)
{
    (void)in_sizes; (void)n_in; (void)out_size;
    const float* x   = (const float*)d_in[0];
    const float* Wf  = (const float*)d_in[1];
    const float* Uf  = (const float*)d_in[2];
    const float* bf  = (const float*)d_in[3];
    const float* Wi  = (const float*)d_in[4];
    const float* Ui  = (const float*)d_in[5];
    const float* bi  = (const float*)d_in[6];
    const float* Wc  = (const float*)d_in[7];
    const float* Uc  = (const float*)d_in[8];
    const float* bc  = (const float*)d_in[9];
    const float* Wo  = (const float*)d_in[10];
    const float* Uo  = (const float*)d_in[11];
    const float* bo  = (const float*)d_in[12];
    const float* Why = (const float*)d_in[13];
    const float* by  = (const float*)d_in[14];
    float* out = (float*)d_out;

    pack_kernel<<<1024, 256>>>(Wf, Uf, bf, Wi, Ui, bi, Wc, Uc, bc, Wo, Uo, bo);

    dim3 g1(2048, 8);
    xproj_kernel<<<g1, 256>>>(x);

    int smem = 128 * 128 * (int)sizeof(float);   // 64KB dynamic (smU)
    cudaFuncSetAttribute(rnn_kernel, cudaFuncAttributeMaxDynamicSharedMemorySize, smem);
    rnn_kernel<<<128, 256, smem>>>();

    out_kernel<<<64, 256>>>(Why, by, out);
}